// round 14
// baseline (speedup 1.0000x reference)
#include <cuda_runtime.h>
#include <cuda_fp16.h>
#include <cstdint>
#include <cstddef>

#define BB   64
#define TDEC 400
#define TENC 512
#define DD   256
#define PRE  128
#define ODIM 400
#define CIN  (PRE + DD)   // 384
#define GRID 128
#define NTH  512

__device__ float  g_pre1[BB * TDEC * DD];
__device__ float  g_p[BB * TDEC * PRE];
__device__ __half g_keysh[BB * TENC * DD];
__device__ __half g_memh[BB * TENC * DD];
__device__ float  g_k0T[3 * DD * CIN];
__device__ float  g_r0T[3 * DD * DD];
__device__ float  g_k1T[3 * DD * DD];
__device__ float  g_r1T[3 * DD * DD];
__device__ float  g_WqT[DD * DD];
__device__ float  g_WaT[DD * 2 * DD];
__device__ float  g_WoT[ODIM * DD];
__device__ float  g_h0[2][BB * DD];
__device__ float  g_h1[2][BB * DD];
__device__ float  g_att[2][BB * DD];
__device__ float  g_q[BB * DD];
__device__ float  g_ctxpart[BB * 2 * DD];   // unnormalized
__device__ float  g_l[BB * 2];              // partial softmax sums
__device__ unsigned g_leaf[16];
__device__ unsigned g_root;
__device__ unsigned g_rel;
__device__ unsigned g_pairCnt[BB];

__device__ __forceinline__ float warp_sum_f(float v) {
#pragma unroll
    for (int o = 16; o; o >>= 1) v += __shfl_xor_sync(0xffffffffu, v, o);
    return v;
}
__device__ __forceinline__ float sigm_f(float x) { return 1.0f / (1.0f + __expf(-x)); }
__device__ __forceinline__ float tanh_f(float x) {
    float e = __expf(2.0f * x);
    return 1.0f - __fdividef(2.0f, e + 1.0f);
}
__device__ __forceinline__ float tanha_f(float x) {
    float y;
    asm("tanh.approx.f32 %0, %1;" : "=f"(y) : "f"(x));
    return y;
}
__device__ __forceinline__ float dot4(float4 a, float4 b) {
    return fmaf(a.x, b.x, fmaf(a.y, b.y, fmaf(a.z, b.z, a.w * b.w)));
}
// hierarchical grid barrier: 16 leaves x 8 CTAs -> root -> release word
__device__ __forceinline__ void grid_sync(unsigned epoch, int leaf) {
    __syncthreads();
    if (threadIdx.x == 0) {
        __threadfence();
        unsigned a = atomicAdd(&g_leaf[leaf], 1u) + 1u;
        if (a == epoch * 8u) {
            unsigned r = atomicAdd(&g_root, 1u) + 1u;
            if (r == epoch * 16u) *(volatile unsigned*)&g_rel = epoch;
        }
        while (*(volatile unsigned*)&g_rel < epoch) { __nanosleep(32); }
        __threadfence();
    }
    __syncthreads();
}

// -------- launch #1: init + all weight transposes + fp16 memory --------------
__global__ void dec_setup_kernel(const float* __restrict__ k0,
                                 const float* __restrict__ r0,
                                 const float* __restrict__ k1,
                                 const float* __restrict__ r1,
                                 const float* __restrict__ Wq,
                                 const float* __restrict__ Wa,
                                 const float* __restrict__ Wo,
                                 const float* __restrict__ memory) {
    int tid = blockIdx.x * blockDim.x + threadIdx.x;
    int nt = gridDim.x * blockDim.x;
    if (tid < 16) g_leaf[tid] = 0;
    if (tid == 16) g_root = 0;
    if (tid == 17) g_rel = 0;
    if (tid < BB) g_pairCnt[tid] = 0;
    for (int i = tid; i < BB * DD; i += nt) {
        g_h0[0][i] = 0.f; g_h1[0][i] = 0.f; g_att[0][i] = 0.f;
    }
    for (int i = tid; i < CIN * 768; i += nt) {
        int r = i / 768, c = i - r * 768;
        g_k0T[c * CIN + r] = k0[i];
    }
    for (int i = tid; i < DD * 768; i += nt) {
        int r = i / 768, c = i - r * 768;
        g_r0T[c * DD + r] = r0[i];
        g_k1T[c * DD + r] = k1[i];
        g_r1T[c * DD + r] = r1[i];
    }
    for (int i = tid; i < DD * DD; i += nt) {
        int r = i >> 8, c = i & 255;
        g_WqT[c * DD + r] = Wq[i];
    }
    for (int i = tid; i < 2 * DD * DD; i += nt) {
        int r = i >> 8, c = i & 255;
        g_WaT[c * 2 * DD + r] = Wa[i];
    }
    for (int i = tid; i < DD * ODIM; i += nt) {
        int r = i / ODIM, c = i - r * ODIM;
        g_WoT[c * DD + r] = Wo[i];
    }
    for (int i = tid; i < BB * TENC * DD; i += nt)
        g_memh[i] = __float2half(memory[i]);
}

// -------- launches #2/#3: SGEMM 128x128x8 (flat job decode) ------------------
__global__ __launch_bounds__(256) void dec_gemm_kernel(
    const float* __restrict__ dec, const float* __restrict__ memory,
    const float* __restrict__ W1, const float* __restrict__ b1,
    const float* __restrict__ Wm, const float* __restrict__ W2,
    const float* __restrict__ b2, int phase)
{
    const float *A, *Bm, *bias; float* C = 0; __half* Ch = 0;
    int N, K, relu, t;
    if (phase == 0) {
        if (blockIdx.x < 400) {
            A = dec; Bm = W1; bias = b1; C = g_pre1;
            N = DD; K = ODIM; relu = 1; t = blockIdx.x;
        } else {
            A = memory; Bm = Wm; bias = 0; Ch = g_keysh;
            N = DD; K = DD; relu = 0; t = blockIdx.x - 400;
        }
    } else {
        A = g_pre1; Bm = W2; bias = b2; C = g_p;
        N = PRE; K = DD; relu = 1; t = blockIdx.x;
    }
    int ntx = N >> 7;
    int n0 = (t % ntx) * 128, m0 = (t / ntx) * 128;

    __shared__ float As[8][128];
    __shared__ float Bs[8][128];
    const int tid = threadIdx.x;
    const int ty = tid / 16, txx = tid & 15;
    const int arow = tid >> 1, acol = (tid & 1) * 4;
    const int brow = tid >> 5, bcol = (tid & 31) * 4;
    float acc[8][8];
#pragma unroll
    for (int i = 0; i < 8; ++i)
#pragma unroll
        for (int j = 0; j < 8; ++j) acc[i][j] = 0.f;

    for (int k0i = 0; k0i < K; k0i += 8) {
        float4 a4 = *reinterpret_cast<const float4*>(&A[(size_t)(m0 + arow) * K + k0i + acol]);
        As[acol + 0][arow] = a4.x; As[acol + 1][arow] = a4.y;
        As[acol + 2][arow] = a4.z; As[acol + 3][arow] = a4.w;
        float4 b4 = *reinterpret_cast<const float4*>(&Bm[(size_t)(k0i + brow) * N + n0 + bcol]);
        *reinterpret_cast<float4*>(&Bs[brow][bcol]) = b4;
        __syncthreads();
#pragma unroll
        for (int k = 0; k < 8; ++k) {
            float af[8], bf[8];
#pragma unroll
            for (int i = 0; i < 8; ++i) af[i] = As[k][ty * 8 + i];
#pragma unroll
            for (int j = 0; j < 8; ++j) bf[j] = Bs[k][txx * 8 + j];
#pragma unroll
            for (int i = 0; i < 8; ++i)
#pragma unroll
                for (int j = 0; j < 8; ++j) acc[i][j] = fmaf(af[i], bf[j], acc[i][j]);
        }
        __syncthreads();
    }
#pragma unroll
    for (int i = 0; i < 8; ++i) {
        int m = m0 + ty * 8 + i;
#pragma unroll
        for (int j = 0; j < 8; ++j) {
            int n = n0 + txx * 8 + j;
            float c = acc[i][j] + (bias ? bias[n] : 0.f);
            if (relu) c = fmaxf(c, 0.f);
            if (Ch) Ch[(size_t)m * N + n] = __float2half(c);
            else    C[(size_t)m * N + n] = c;
        }
    }
}

// -------- launch #4: persistent decoder --------------------------------------
__global__ __launch_bounds__(NTH) void dec_main_kernel(
    const float* __restrict__ bi0, const float* __restrict__ br0,
    const float* __restrict__ bi1, const float* __restrict__ br1,
    const float* __restrict__ v,   const float* __restrict__ bo,
    float* __restrict__ out)
{
    const int cta  = blockIdx.x;
    const int tid  = threadIdx.x;
    const int warp = tid >> 5, lane = tid & 31;
    const int d0   = cta * 2;
    const int leaf = cta >> 3;
    unsigned ep = 0;

    __shared__ float s_k0[3 * 2 * CIN];
    __shared__ float s_r0[3 * 2 * DD];
    __shared__ float s_k1[3 * 2 * DD];
    __shared__ float s_r1[3 * 2 * DD];
    __shared__ float s_wa[2 * 2 * DD];
    __shared__ float s_wo[4 * DD];
    __shared__ float s_q[DD];
    __shared__ float s_sc[DD];
    __shared__ float s_v[DD];
    __shared__ float s_cx[4 * DD];
    __shared__ float s_red[16];

    for (int i = tid; i < 3 * 2 * CIN; i += NTH) {
        int g = i / (2 * CIN); int rem = i - g * 2 * CIN;
        int ds = rem / CIN;    int k = rem - ds * CIN;
        s_k0[i] = g_k0T[(g * DD + d0 + ds) * CIN + k];
    }
    for (int i = tid; i < 3 * 2 * DD; i += NTH) {
        int g = i / (2 * DD); int rem = i - g * 2 * DD;
        int ds = rem / DD;    int k = rem - ds * DD;
        s_r0[i] = g_r0T[(g * DD + d0 + ds) * DD + k];
        s_k1[i] = g_k1T[(g * DD + d0 + ds) * DD + k];
        s_r1[i] = g_r1T[(g * DD + d0 + ds) * DD + k];
    }
    for (int i = tid; i < 2 * 2 * DD; i += NTH) {
        int ds = i / (2 * DD); int k = i - ds * 2 * DD;
        s_wa[i] = g_WaT[(d0 + ds) * 2 * DD + k];
    }
    if (cta < 100) {
        for (int i = tid; i < 4 * DD; i += NTH) {
            int jj = i / DD; int k = i - jj * DD;
            s_wo[i] = g_WoT[(cta * 4 + jj) * DD + k];
        }
    }
    for (int i = tid; i < DD; i += NTH) s_v[i] = v[i];
    __syncthreads();

    float S = 0.f;
    for (int i = 0; i < DD; ++i) S += fabsf(s_v[i]);
    float vr[8];
#pragma unroll
    for (int j = 0; j < 8; ++j) vr[j] = s_v[lane * 8 + j];

    for (int step = 0; step < TDEC; ++step) {
        const int par = step & 1;
        const float* h0c  = g_h0[par];    float* h0n  = g_h0[par ^ 1];
        const float* h1c  = g_h1[par];    float* h1n  = g_h1[par ^ 1];
        const float* attc = g_att[par];   float* attn_ = g_att[par ^ 1];

        // ============ P1: GRU0 (+ output dense for step-1) ==================
        {
            const int ds = warp & 1, d = d0 + ds, bg = warp >> 1;
            float4 wz[3], wr_[3], wh[3], uz[2], ur_[2], uh[2];
#pragma unroll
            for (int c = 0; c < 3; ++c) {
                wz[c]  = *reinterpret_cast<const float4*>(&s_k0[(0 * 2 + ds) * CIN + c * 128 + lane * 4]);
                wr_[c] = *reinterpret_cast<const float4*>(&s_k0[(1 * 2 + ds) * CIN + c * 128 + lane * 4]);
                wh[c]  = *reinterpret_cast<const float4*>(&s_k0[(2 * 2 + ds) * CIN + c * 128 + lane * 4]);
            }
#pragma unroll
            for (int c = 0; c < 2; ++c) {
                uz[c]  = *reinterpret_cast<const float4*>(&s_r0[(0 * 2 + ds) * DD + c * 128 + lane * 4]);
                ur_[c] = *reinterpret_cast<const float4*>(&s_r0[(1 * 2 + ds) * DD + c * 128 + lane * 4]);
                uh[c]  = *reinterpret_cast<const float4*>(&s_r0[(2 * 2 + ds) * DD + c * 128 + lane * 4]);
            }
            const float bz  = bi0[d] + br0[d];
            const float brg = bi0[DD + d] + br0[DD + d];
            const float bih = bi0[2 * DD + d], brh = br0[2 * DD + d];
#pragma unroll 2
            for (int bi = 0; bi < 8; ++bi) {
                int b = bg * 8 + bi;
                const float4* pb = reinterpret_cast<const float4*>(&g_p[(b * TDEC + step) * PRE]);
                const float4* ab = reinterpret_cast<const float4*>(&attc[b * DD]);
                const float4* hb = reinterpret_cast<const float4*>(&h0c[b * DD]);
                float4 x0 = pb[lane];
                float4 x1 = ab[lane], x2 = ab[32 + lane];
                float4 h1v = hb[lane], h2v = hb[32 + lane];
                float az = dot4(x0, wz[0])  + dot4(x1, wz[1])  + dot4(x2, wz[2]);
                float ar = dot4(x0, wr_[0]) + dot4(x1, wr_[1]) + dot4(x2, wr_[2]);
                float ah = dot4(x0, wh[0])  + dot4(x1, wh[1])  + dot4(x2, wh[2]);
                float gz = dot4(h1v, uz[0])  + dot4(h2v, uz[1]);
                float gr = dot4(h1v, ur_[0]) + dot4(h2v, ur_[1]);
                float gh = dot4(h1v, uh[0])  + dot4(h2v, uh[1]);
                float sz = az + gz, sr = ar + gr;
#pragma unroll
                for (int off = 16; off; off >>= 1) {
                    sz += __shfl_xor_sync(0xffffffffu, sz, off);
                    sr += __shfl_xor_sync(0xffffffffu, sr, off);
                    ah += __shfl_xor_sync(0xffffffffu, ah, off);
                    gh += __shfl_xor_sync(0xffffffffu, gh, off);
                }
                if (lane == 0) {
                    float z = sigm_f(sz + bz);
                    float r = sigm_f(sr + brg);
                    float hc = tanh_f(ah + bih + r * (gh + brh));
                    h0n[b * DD + d] = z * h0c[b * DD + d] + (1.0f - z) * hc;
                }
            }
            if (cta < 100 && step > 0) {
                const int jj = warp & 3, j = cta * 4 + jj, bg2 = warp >> 2;
                float4 wo0 = *reinterpret_cast<const float4*>(&s_wo[jj * DD + lane * 4]);
                float4 wo1 = *reinterpret_cast<const float4*>(&s_wo[jj * DD + 128 + lane * 4]);
                const float boj = bo[j];
#pragma unroll 2
                for (int bi = 0; bi < 16; ++bi) {
                    int b = bg2 * 16 + bi;
                    const float4* arow = reinterpret_cast<const float4*>(&attc[b * DD]);
                    float a = dot4(arow[lane], wo0) + dot4(arow[32 + lane], wo1);
                    a = warp_sum_f(a);
                    if (lane == 0)
                        out[(size_t)(b * TDEC + (step - 1)) * ODIM + j] = a + boj;
                }
            }
        }
        grid_sync(++ep, leaf);

        // ============ P2: GRU1 ===============================================
        {
            const int ds = warp & 1, d = d0 + ds, bg = warp >> 1;
            float4 wk[3][2], ur[3][2];
#pragma unroll
            for (int g = 0; g < 3; ++g)
#pragma unroll
                for (int c = 0; c < 2; ++c) {
                    wk[g][c] = *reinterpret_cast<const float4*>(&s_k1[(g * 2 + ds) * DD + c * 128 + lane * 4]);
                    ur[g][c] = *reinterpret_cast<const float4*>(&s_r1[(g * 2 + ds) * DD + c * 128 + lane * 4]);
                }
            const float bz  = bi1[d] + br1[d];
            const float brg = bi1[DD + d] + br1[DD + d];
            const float bih = bi1[2 * DD + d], brh = br1[2 * DD + d];
#pragma unroll 2
            for (int bi = 0; bi < 8; ++bi) {
                int b = bg * 8 + bi;
                const float4* xb = reinterpret_cast<const float4*>(&h0n[b * DD]);
                const float4* hb = reinterpret_cast<const float4*>(&h1c[b * DD]);
                float4 x0 = xb[lane], x1 = xb[32 + lane];
                float4 h0v = hb[lane], h1v = hb[32 + lane];
                float az = dot4(x0, wk[0][0]) + dot4(x1, wk[0][1]);
                float ar = dot4(x0, wk[1][0]) + dot4(x1, wk[1][1]);
                float ah = dot4(x0, wk[2][0]) + dot4(x1, wk[2][1]);
                float gz = dot4(h0v, ur[0][0]) + dot4(h1v, ur[0][1]);
                float gr = dot4(h0v, ur[1][0]) + dot4(h1v, ur[1][1]);
                float gh = dot4(h0v, ur[2][0]) + dot4(h1v, ur[2][1]);
                float sz = az + gz, sr = ar + gr;
#pragma unroll
                for (int off = 16; off; off >>= 1) {
                    sz += __shfl_xor_sync(0xffffffffu, sz, off);
                    sr += __shfl_xor_sync(0xffffffffu, sr, off);
                    ah += __shfl_xor_sync(0xffffffffu, ah, off);
                    gh += __shfl_xor_sync(0xffffffffu, gh, off);
                }
                if (lane == 0) {
                    float z = sigm_f(sz + bz);
                    float r = sigm_f(sr + brg);
                    float hc = tanh_f(ah + bih + r * (gh + brh));
                    h1n[b * DD + d] = z * h1c[b * DD + d] + (1.0f - z) * hc;
                }
            }
        }
        grid_sync(++ep, leaf);

        // ============ P3: q-half + fp16-key scores (fixed shift) + ctx =======
        {
            const int b = cta >> 1, half = cta & 1;
            const int tbase = half * 256;
            {
                const float4* hb = reinterpret_cast<const float4*>(&h1n[b * DD]);
                float4 h0v = hb[lane], h1v = hb[32 + lane];
#pragma unroll 2
                for (int qi = 0; qi < 8; ++qi) {
                    int dq = half * 128 + warp * 8 + qi;
                    const float4* wr = reinterpret_cast<const float4*>(&g_WqT[dq * DD]);
                    float a = dot4(h0v, wr[lane]) + dot4(h1v, wr[32 + lane]);
                    a = warp_sum_f(a);
                    if (lane == 0) { g_q[b * DD + dq] = a; s_q[dq] = a; }
                }
            }
            __syncthreads();
            if (tid == 0) {
                __threadfence();
                atomicAdd(&g_pairCnt[b], 1u);
                unsigned tgt = 2u * (unsigned)step + 2u;
                while (*(volatile unsigned*)&g_pairCnt[b] < tgt) { __nanosleep(32); }
                __threadfence();
            }
            __syncthreads();
            if (tid < 128) {
                int oh = half ^ 1;
                s_q[oh * 128 + tid] = g_q[b * DD + oh * 128 + tid];
            }
            __syncthreads();
            float qr[8];
#pragma unroll
            for (int j = 0; j < 8; ++j) qr[j] = s_q[lane * 8 + j];
            float esum = 0.f;
#pragma unroll 2
            for (int ti = 0; ti < 16; ++ti) {
                int tt = warp * 16 + ti;
                const uint4 kk = *(reinterpret_cast<const uint4*>(
                    &g_keysh[(size_t)(b * TENC + tbase + tt) * DD]) + lane);
                const __half2* kh = reinterpret_cast<const __half2*>(&kk);
                float a = 0.f;
#pragma unroll
                for (int j = 0; j < 4; ++j) {
                    float2 kf = __half22float2(kh[j]);
                    a = fmaf(tanha_f(kf.x + qr[2 * j]),     vr[2 * j],     a);
                    a = fmaf(tanha_f(kf.y + qr[2 * j + 1]), vr[2 * j + 1], a);
                }
                a = warp_sum_f(a);
                if (lane == 0) {
                    float e = __expf(a - S);
                    s_sc[tt] = e;
                    esum += e;
                }
            }
            if (lane == 0) s_red[warp] = esum;
            __syncthreads();
            if (tid == 0) {
                float l = 0.f;
#pragma unroll
                for (int i = 0; i < 16; ++i) l += s_red[i];
                g_l[b * 2 + half] = l;
            }
            {
                int dp = tid & 127, tg = tid >> 7;   // 4 t-groups x 128 d-pairs
                const __half2* mb = reinterpret_cast<const __half2*>(
                    &g_memh[(size_t)(b * TENC + tbase + tg * 64) * DD]) + dp;
                const int sb = tg * 64;
                float ax = 0.f, ay = 0.f;
#pragma unroll 8
                for (int t = 0; t < 64; ++t) {
                    float2 mf = __half22float2(mb[t * 128]);
                    float sc = s_sc[sb + t];
                    ax = fmaf(sc, mf.x, ax);
                    ay = fmaf(sc, mf.y, ay);
                }
                s_cx[tg * 256 + dp * 2]     = ax;
                s_cx[tg * 256 + dp * 2 + 1] = ay;
            }
            __syncthreads();
            if (tid < 256)
                g_ctxpart[(b * 2 + half) * DD + tid] =
                    s_cx[tid] + s_cx[256 + tid] + s_cx[512 + tid] + s_cx[768 + tid];
        }
        grid_sync(++ep, leaf);

        // ============ P4: attention dense (normalizes ctx) ===================
        {
            const int ds = warp & 1, d = d0 + ds, bg = warp >> 1;
            float4 wa1[2], wa2[2];
#pragma unroll
            for (int c = 0; c < 2; ++c) {
                wa1[c] = *reinterpret_cast<const float4*>(&s_wa[ds * 2 * DD + c * 128 + lane * 4]);
                wa2[c] = *reinterpret_cast<const float4*>(&s_wa[ds * 2 * DD + DD + c * 128 + lane * 4]);
            }
#pragma unroll 2
            for (int bi = 0; bi < 8; ++bi) {
                int b = bg * 8 + bi;
                float inv_l = __fdividef(1.0f, g_l[b * 2] + g_l[b * 2 + 1]);
                const float4* hb = reinterpret_cast<const float4*>(&h1n[b * DD]);
                const float4* c0 = reinterpret_cast<const float4*>(&g_ctxpart[(b * 2 + 0) * DD]);
                const float4* c1 = reinterpret_cast<const float4*>(&g_ctxpart[(b * 2 + 1) * DD]);
                float a = 0;
#pragma unroll
                for (int c = 0; c < 2; ++c) {
                    float4 h4 = hb[c * 32 + lane];
                    a += dot4(h4, wa1[c]);
                    float4 a4 = c0[c * 32 + lane];
                    float4 b4 = c1[c * 32 + lane];
                    float4 x = make_float4((a4.x + b4.x) * inv_l, (a4.y + b4.y) * inv_l,
                                           (a4.z + b4.z) * inv_l, (a4.w + b4.w) * inv_l);
                    a += dot4(x, wa2[c]);
                }
                a = warp_sum_f(a);
                if (lane == 0) attn_[b * DD + d] = a;
            }
        }
        grid_sync(++ep, leaf);
    }

    // final y for step 399 (attn(399) lives in g_att[0])
    if (cta < 100) {
        const float* attc = g_att[0];
        const int jj = warp & 3, j = cta * 4 + jj, bg2 = warp >> 2;
        float4 wo0 = *reinterpret_cast<const float4*>(&s_wo[jj * DD + lane * 4]);
        float4 wo1 = *reinterpret_cast<const float4*>(&s_wo[jj * DD + 128 + lane * 4]);
        const float boj = bo[j];
        for (int bi = 0; bi < 16; ++bi) {
            int b = bg2 * 16 + bi;
            const float4* arow = reinterpret_cast<const float4*>(&attc[b * DD]);
            float a = dot4(arow[lane], wo0) + dot4(arow[32 + lane], wo1);
            a = warp_sum_f(a);
            if (lane == 0)
                out[(size_t)(b * TDEC + (TDEC - 1)) * ODIM + j] = a + boj;
        }
    }
}

// ---------------- launch ------------------------------------------------------
extern "C" void kernel_launch(void* const* d_in, const int* in_sizes, int n_in,
                              void* d_out, int out_size) {
    (void)in_sizes; (void)n_in; (void)out_size;
    const float* dec    = (const float*)d_in[0];
    const float* memory = (const float*)d_in[1];
    const float* W1  = (const float*)d_in[2];
    const float* b1  = (const float*)d_in[3];
    const float* W2  = (const float*)d_in[4];
    const float* b2  = (const float*)d_in[5];
    const float* k0  = (const float*)d_in[6];
    const float* r0  = (const float*)d_in[7];
    const float* bi0 = (const float*)d_in[8];
    const float* br0 = (const float*)d_in[9];
    const float* k1  = (const float*)d_in[10];
    const float* r1  = (const float*)d_in[11];
    const float* bi1 = (const float*)d_in[12];
    const float* br1 = (const float*)d_in[13];
    const float* Wq  = (const float*)d_in[14];
    const float* Wm  = (const float*)d_in[15];
    const float* v   = (const float*)d_in[16];
    const float* Wa  = (const float*)d_in[17];
    const float* Wo  = (const float*)d_in[18];
    const float* bo  = (const float*)d_in[19];
    float* out = (float*)d_out;

    dec_setup_kernel<<<1024, 256>>>(k0, r0, k1, r1, Wq, Wa, Wo, memory);    // #1
    dec_gemm_kernel<<<912, 256>>>(dec, memory, W1, b1, Wm, W2, b2, 0);      // #2
    dec_gemm_kernel<<<200, 256>>>(dec, memory, W1, b1, Wm, W2, b2, 1);      // #3
    dec_main_kernel<<<GRID, NTH>>>(bi0, br0, bi1, br1, v, bo, out);         // #4
}

// round 15
// speedup vs baseline: 1.0460x; 1.0460x over previous
#include <cuda_runtime.h>
#include <cuda_fp16.h>
#include <cstdint>
#include <cstddef>

#define BB   64
#define TDEC 400
#define TENC 512
#define DD   256
#define PRE  128
#define ODIM 400
#define CIN  (PRE + DD)   // 384
#define GRID 128
#define NTH  512

__device__ float  g_pre1[BB * TDEC * DD];
__device__ float  g_p[BB * TDEC * PRE];
__device__ float  g_keys[BB * TENC * DD];
__device__ __half g_memh[BB * TENC * DD];
__device__ float  g_k0T[3 * DD * CIN];
__device__ float  g_r0T[3 * DD * DD];
__device__ float  g_k1T[3 * DD * DD];
__device__ float  g_r1T[3 * DD * DD];
__device__ float  g_WqT[DD * DD];
__device__ float  g_WaT[DD * 2 * DD];
__device__ float  g_WoT[ODIM * DD];
__device__ float  g_h0[2][BB * DD];
__device__ float  g_h1[2][BB * DD];
__device__ float  g_att[2][BB * DD];
__device__ float  g_q[BB * DD];
__device__ float  g_ctxpart[BB * 2 * DD];   // unnormalized
__device__ float  g_l[BB * 2];              // partial softmax sums
__device__ unsigned g_barArrive;
__device__ unsigned g_pairCnt[BB];

__device__ __forceinline__ float warp_sum_f(float v) {
#pragma unroll
    for (int o = 16; o; o >>= 1) v += __shfl_xor_sync(0xffffffffu, v, o);
    return v;
}
__device__ __forceinline__ float sigm_f(float x) { return 1.0f / (1.0f + __expf(-x)); }
__device__ __forceinline__ float tanh_f(float x) {
    float e = __expf(2.0f * x);
    return 1.0f - __fdividef(2.0f, e + 1.0f);
}
__device__ __forceinline__ float tanha_f(float x) {
    float y;
    asm("tanh.approx.f32 %0, %1;" : "=f"(y) : "f"(x));
    return y;
}
__device__ __forceinline__ float dot4(float4 a, float4 b) {
    return fmaf(a.x, b.x, fmaf(a.y, b.y, fmaf(a.z, b.z, a.w * b.w)));
}
__device__ __forceinline__ void grid_sync(unsigned epoch) {
    __syncthreads();
    if (threadIdx.x == 0) {
        __threadfence();
        atomicAdd(&g_barArrive, 1u);
        unsigned tgt = epoch * (unsigned)GRID;
        while (*(volatile unsigned*)&g_barArrive < tgt) { __nanosleep(32); }
        __threadfence();
    }
    __syncthreads();
}

// -------- launch #1: init + all weight transposes + fp16 memory --------------
__global__ void dec_setup_kernel(const float* __restrict__ k0,
                                 const float* __restrict__ r0,
                                 const float* __restrict__ k1,
                                 const float* __restrict__ r1,
                                 const float* __restrict__ Wq,
                                 const float* __restrict__ Wa,
                                 const float* __restrict__ Wo,
                                 const float* __restrict__ memory) {
    int tid = blockIdx.x * blockDim.x + threadIdx.x;
    int nt = gridDim.x * blockDim.x;
    if (tid == 0) g_barArrive = 0;
    if (tid < BB) g_pairCnt[tid] = 0;
    for (int i = tid; i < BB * DD; i += nt) {
        g_h0[0][i] = 0.f; g_h1[0][i] = 0.f; g_att[0][i] = 0.f;
    }
    for (int i = tid; i < CIN * 768; i += nt) {
        int r = i / 768, c = i - r * 768;
        g_k0T[c * CIN + r] = k0[i];
    }
    for (int i = tid; i < DD * 768; i += nt) {
        int r = i / 768, c = i - r * 768;
        g_r0T[c * DD + r] = r0[i];
        g_k1T[c * DD + r] = k1[i];
        g_r1T[c * DD + r] = r1[i];
    }
    for (int i = tid; i < DD * DD; i += nt) {
        int r = i >> 8, c = i & 255;
        g_WqT[c * DD + r] = Wq[i];
    }
    for (int i = tid; i < 2 * DD * DD; i += nt) {
        int r = i >> 8, c = i & 255;
        g_WaT[c * 2 * DD + r] = Wa[i];
    }
    for (int i = tid; i < DD * ODIM; i += nt) {
        int r = i / ODIM, c = i - r * ODIM;
        g_WoT[c * DD + r] = Wo[i];
    }
    for (int i = tid; i < BB * TENC * DD; i += nt)
        g_memh[i] = __float2half(memory[i]);
}

// -------- launches #2/#3: SGEMM 128x128x8 (flat job decode) ------------------
__global__ __launch_bounds__(256) void dec_gemm_kernel(
    const float* __restrict__ dec, const float* __restrict__ memory,
    const float* __restrict__ W1, const float* __restrict__ b1,
    const float* __restrict__ Wm, const float* __restrict__ W2,
    const float* __restrict__ b2, int phase)
{
    const float *A, *Bm, *bias; float* C;
    int N, K, relu, t;
    if (phase == 0) {
        if (blockIdx.x < 400) {
            A = dec; Bm = W1; bias = b1; C = g_pre1;
            N = DD; K = ODIM; relu = 1; t = blockIdx.x;
        } else {
            A = memory; Bm = Wm; bias = 0; C = g_keys;
            N = DD; K = DD; relu = 0; t = blockIdx.x - 400;
        }
    } else {
        A = g_pre1; Bm = W2; bias = b2; C = g_p;
        N = PRE; K = DD; relu = 1; t = blockIdx.x;
    }
    int ntx = N >> 7;
    int n0 = (t % ntx) * 128, m0 = (t / ntx) * 128;

    __shared__ float As[8][128];
    __shared__ float Bs[8][128];
    const int tid = threadIdx.x;
    const int ty = tid / 16, txx = tid & 15;
    const int arow = tid >> 1, acol = (tid & 1) * 4;
    const int brow = tid >> 5, bcol = (tid & 31) * 4;
    float acc[8][8];
#pragma unroll
    for (int i = 0; i < 8; ++i)
#pragma unroll
        for (int j = 0; j < 8; ++j) acc[i][j] = 0.f;

    for (int k0i = 0; k0i < K; k0i += 8) {
        float4 a4 = *reinterpret_cast<const float4*>(&A[(size_t)(m0 + arow) * K + k0i + acol]);
        As[acol + 0][arow] = a4.x; As[acol + 1][arow] = a4.y;
        As[acol + 2][arow] = a4.z; As[acol + 3][arow] = a4.w;
        float4 b4 = *reinterpret_cast<const float4*>(&Bm[(size_t)(k0i + brow) * N + n0 + bcol]);
        *reinterpret_cast<float4*>(&Bs[brow][bcol]) = b4;
        __syncthreads();
#pragma unroll
        for (int k = 0; k < 8; ++k) {
            float af[8], bf[8];
#pragma unroll
            for (int i = 0; i < 8; ++i) af[i] = As[k][ty * 8 + i];
#pragma unroll
            for (int j = 0; j < 8; ++j) bf[j] = Bs[k][txx * 8 + j];
#pragma unroll
            for (int i = 0; i < 8; ++i)
#pragma unroll
                for (int j = 0; j < 8; ++j) acc[i][j] = fmaf(af[i], bf[j], acc[i][j]);
        }
        __syncthreads();
    }
#pragma unroll
    for (int i = 0; i < 8; ++i) {
        int m = m0 + ty * 8 + i;
#pragma unroll
        for (int j = 0; j < 8; ++j) {
            int n = n0 + txx * 8 + j;
            float c = acc[i][j] + (bias ? bias[n] : 0.f);
            if (relu) c = fmaxf(c, 0.f);
            C[(size_t)m * N + n] = c;
        }
    }
}

// -------- launch #4: persistent decoder --------------------------------------
__global__ __launch_bounds__(NTH) void dec_main_kernel(
    const float* __restrict__ bi0, const float* __restrict__ br0,
    const float* __restrict__ bi1, const float* __restrict__ br1,
    const float* __restrict__ v,   const float* __restrict__ bo,
    float* __restrict__ out)
{
    extern __shared__ float s_wq[];    // 128 rows x 256 floats = 128 KB dynamic

    const int cta  = blockIdx.x;
    const int tid  = threadIdx.x;
    const int warp = tid >> 5, lane = tid & 31;
    const int d0   = cta * 2;
    unsigned ep = 0;

    __shared__ float s_k0[3 * 2 * CIN];
    __shared__ float s_r0[3 * 2 * DD];
    __shared__ float s_k1[3 * 2 * DD];
    __shared__ float s_r1[3 * 2 * DD];
    __shared__ float s_wa[2 * 2 * DD];
    __shared__ float s_wo[4 * DD];
    __shared__ float s_q[DD];
    __shared__ float s_sc[DD];
    __shared__ float s_v[DD];
    __shared__ float s_cx[4 * DD];
    __shared__ float s_red[16];

    for (int i = tid; i < 3 * 2 * CIN; i += NTH) {
        int g = i / (2 * CIN); int rem = i - g * 2 * CIN;
        int ds = rem / CIN;    int k = rem - ds * CIN;
        s_k0[i] = g_k0T[(g * DD + d0 + ds) * CIN + k];
    }
    for (int i = tid; i < 3 * 2 * DD; i += NTH) {
        int g = i / (2 * DD); int rem = i - g * 2 * DD;
        int ds = rem / DD;    int k = rem - ds * DD;
        s_r0[i] = g_r0T[(g * DD + d0 + ds) * DD + k];
        s_k1[i] = g_k1T[(g * DD + d0 + ds) * DD + k];
        s_r1[i] = g_r1T[(g * DD + d0 + ds) * DD + k];
    }
    for (int i = tid; i < 2 * 2 * DD; i += NTH) {
        int ds = i / (2 * DD); int k = i - ds * 2 * DD;
        s_wa[i] = g_WaT[(d0 + ds) * 2 * DD + k];
    }
    if (cta < 100) {
        for (int i = tid; i < 4 * DD; i += NTH) {
            int jj = i / DD; int k = i - jj * DD;
            s_wo[i] = g_WoT[(cta * 4 + jj) * DD + k];
        }
    }
    for (int i = tid; i < DD; i += NTH) s_v[i] = v[i];
    {   // this CTA's fixed q-half Wq rows, resident all 400 steps
        const int half0 = cta & 1;
        for (int i = tid; i < 128 * DD; i += NTH)
            s_wq[i] = g_WqT[(half0 * 128) * DD + i];
    }
    __syncthreads();

    float S = 0.f;
    for (int i = 0; i < DD; ++i) S += fabsf(s_v[i]);
    float4 v4[2];
#pragma unroll
    for (int c = 0; c < 2; ++c)
        v4[c] = *reinterpret_cast<const float4*>(&s_v[c * 128 + lane * 4]);

    for (int step = 0; step < TDEC; ++step) {
        const int par = step & 1;
        const float* h0c  = g_h0[par];    float* h0n  = g_h0[par ^ 1];
        const float* h1c  = g_h1[par];    float* h1n  = g_h1[par ^ 1];
        const float* attc = g_att[par];   float* attn_ = g_att[par ^ 1];

        // ============ P1: GRU0 (+ output dense for step-1) ==================
        {
            const int ds = warp & 1, d = d0 + ds, bg = warp >> 1;
            float4 wz[3], wr_[3], wh[3], uz[2], ur_[2], uh[2];
#pragma unroll
            for (int c = 0; c < 3; ++c) {
                wz[c]  = *reinterpret_cast<const float4*>(&s_k0[(0 * 2 + ds) * CIN + c * 128 + lane * 4]);
                wr_[c] = *reinterpret_cast<const float4*>(&s_k0[(1 * 2 + ds) * CIN + c * 128 + lane * 4]);
                wh[c]  = *reinterpret_cast<const float4*>(&s_k0[(2 * 2 + ds) * CIN + c * 128 + lane * 4]);
            }
#pragma unroll
            for (int c = 0; c < 2; ++c) {
                uz[c]  = *reinterpret_cast<const float4*>(&s_r0[(0 * 2 + ds) * DD + c * 128 + lane * 4]);
                ur_[c] = *reinterpret_cast<const float4*>(&s_r0[(1 * 2 + ds) * DD + c * 128 + lane * 4]);
                uh[c]  = *reinterpret_cast<const float4*>(&s_r0[(2 * 2 + ds) * DD + c * 128 + lane * 4]);
            }
            const float bz  = bi0[d] + br0[d];
            const float brg = bi0[DD + d] + br0[DD + d];
            const float bih = bi0[2 * DD + d], brh = br0[2 * DD + d];
#pragma unroll 2
            for (int bi = 0; bi < 8; ++bi) {
                int b = bg * 8 + bi;
                const float4* pb = reinterpret_cast<const float4*>(&g_p[(b * TDEC + step) * PRE]);
                const float4* ab = reinterpret_cast<const float4*>(&attc[b * DD]);
                const float4* hb = reinterpret_cast<const float4*>(&h0c[b * DD]);
                float4 x0 = pb[lane];
                float4 x1 = ab[lane], x2 = ab[32 + lane];
                float4 h1v = hb[lane], h2v = hb[32 + lane];
                float az = dot4(x0, wz[0])  + dot4(x1, wz[1])  + dot4(x2, wz[2]);
                float ar = dot4(x0, wr_[0]) + dot4(x1, wr_[1]) + dot4(x2, wr_[2]);
                float ah = dot4(x0, wh[0])  + dot4(x1, wh[1])  + dot4(x2, wh[2]);
                float gz = dot4(h1v, uz[0])  + dot4(h2v, uz[1]);
                float gr = dot4(h1v, ur_[0]) + dot4(h2v, ur_[1]);
                float gh = dot4(h1v, uh[0])  + dot4(h2v, uh[1]);
                float sz = az + gz, sr = ar + gr;
#pragma unroll
                for (int off = 16; off; off >>= 1) {
                    sz += __shfl_xor_sync(0xffffffffu, sz, off);
                    sr += __shfl_xor_sync(0xffffffffu, sr, off);
                    ah += __shfl_xor_sync(0xffffffffu, ah, off);
                    gh += __shfl_xor_sync(0xffffffffu, gh, off);
                }
                if (lane == 0) {
                    float z = sigm_f(sz + bz);
                    float r = sigm_f(sr + brg);
                    float hc = tanh_f(ah + bih + r * (gh + brh));
                    h0n[b * DD + d] = z * h0c[b * DD + d] + (1.0f - z) * hc;
                }
            }
            if (cta < 100 && step > 0) {
                const int jj = warp & 3, j = cta * 4 + jj, bg2 = warp >> 2;
                float4 wo0 = *reinterpret_cast<const float4*>(&s_wo[jj * DD + lane * 4]);
                float4 wo1 = *reinterpret_cast<const float4*>(&s_wo[jj * DD + 128 + lane * 4]);
                const float boj = bo[j];
#pragma unroll 2
                for (int bi = 0; bi < 16; ++bi) {
                    int b = bg2 * 16 + bi;
                    const float4* arow = reinterpret_cast<const float4*>(&attc[b * DD]);
                    float a = dot4(arow[lane], wo0) + dot4(arow[32 + lane], wo1);
                    a = warp_sum_f(a);
                    if (lane == 0)
                        out[(size_t)(b * TDEC + (step - 1)) * ODIM + j] = a + boj;
                }
            }
        }
        grid_sync(++ep);

        // ============ P2: GRU1 ===============================================
        {
            const int ds = warp & 1, d = d0 + ds, bg = warp >> 1;
            float4 wk[3][2], ur[3][2];
#pragma unroll
            for (int g = 0; g < 3; ++g)
#pragma unroll
                for (int c = 0; c < 2; ++c) {
                    wk[g][c] = *reinterpret_cast<const float4*>(&s_k1[(g * 2 + ds) * DD + c * 128 + lane * 4]);
                    ur[g][c] = *reinterpret_cast<const float4*>(&s_r1[(g * 2 + ds) * DD + c * 128 + lane * 4]);
                }
            const float bz  = bi1[d] + br1[d];
            const float brg = bi1[DD + d] + br1[DD + d];
            const float bih = bi1[2 * DD + d], brh = br1[2 * DD + d];
#pragma unroll 2
            for (int bi = 0; bi < 8; ++bi) {
                int b = bg * 8 + bi;
                const float4* xb = reinterpret_cast<const float4*>(&h0n[b * DD]);
                const float4* hb = reinterpret_cast<const float4*>(&h1c[b * DD]);
                float4 x0 = xb[lane], x1 = xb[32 + lane];
                float4 h0v = hb[lane], h1v = hb[32 + lane];
                float az = dot4(x0, wk[0][0]) + dot4(x1, wk[0][1]);
                float ar = dot4(x0, wk[1][0]) + dot4(x1, wk[1][1]);
                float ah = dot4(x0, wk[2][0]) + dot4(x1, wk[2][1]);
                float gz = dot4(h0v, ur[0][0]) + dot4(h1v, ur[0][1]);
                float gr = dot4(h0v, ur[1][0]) + dot4(h1v, ur[1][1]);
                float gh = dot4(h0v, ur[2][0]) + dot4(h1v, ur[2][1]);
                float sz = az + gz, sr = ar + gr;
#pragma unroll
                for (int off = 16; off; off >>= 1) {
                    sz += __shfl_xor_sync(0xffffffffu, sz, off);
                    sr += __shfl_xor_sync(0xffffffffu, sr, off);
                    ah += __shfl_xor_sync(0xffffffffu, ah, off);
                    gh += __shfl_xor_sync(0xffffffffu, gh, off);
                }
                if (lane == 0) {
                    float z = sigm_f(sz + bz);
                    float r = sigm_f(sr + brg);
                    float hc = tanh_f(ah + bih + r * (gh + brh));
                    h1n[b * DD + d] = z * h1c[b * DD + d] + (1.0f - z) * hc;
                }
            }
        }
        grid_sync(++ep);

        // ============ P3: q-half (SMEM Wq) + scores (fixed shift) + ctx ======
        {
            const int b = cta >> 1, half = cta & 1;
            const int tbase = half * 256;
            {
                const float4* hb = reinterpret_cast<const float4*>(&h1n[b * DD]);
                float4 h0v = hb[lane], h1v = hb[32 + lane];
#pragma unroll 2
                for (int qi = 0; qi < 8; ++qi) {
                    int dq = half * 128 + warp * 8 + qi;
                    const float4* wr = reinterpret_cast<const float4*>(&s_wq[(warp * 8 + qi) * DD]);
                    float a = dot4(h0v, wr[lane]) + dot4(h1v, wr[32 + lane]);
                    a = warp_sum_f(a);
                    if (lane == 0) { g_q[b * DD + dq] = a; s_q[dq] = a; }
                }
            }
            __syncthreads();
            if (tid == 0) {
                __threadfence();
                atomicAdd(&g_pairCnt[b], 1u);
                unsigned tgt = 2u * (unsigned)step + 2u;
                while (*(volatile unsigned*)&g_pairCnt[b] < tgt) { __nanosleep(32); }
                __threadfence();
            }
            __syncthreads();
            if (tid < 128) {
                int oh = half ^ 1;
                s_q[oh * 128 + tid] = g_q[b * DD + oh * 128 + tid];
            }
            __syncthreads();
            float4 q4[2];
#pragma unroll
            for (int c = 0; c < 2; ++c)
                q4[c] = *reinterpret_cast<const float4*>(&s_q[c * 128 + lane * 4]);
            float esum = 0.f;
#pragma unroll 2
            for (int ti = 0; ti < 16; ++ti) {
                int tt = warp * 16 + ti;
                const float* krow = &g_keys[(size_t)(b * TENC + tbase + tt) * DD];
                float a = 0;
#pragma unroll
                for (int c = 0; c < 2; ++c) {
                    float4 kk = *reinterpret_cast<const float4*>(&krow[c * 128 + lane * 4]);
                    a += tanha_f(kk.x + q4[c].x) * v4[c].x;
                    a += tanha_f(kk.y + q4[c].y) * v4[c].y;
                    a += tanha_f(kk.z + q4[c].z) * v4[c].z;
                    a += tanha_f(kk.w + q4[c].w) * v4[c].w;
                }
                a = warp_sum_f(a);
                if (lane == 0) {
                    float e = __expf(a - S);
                    s_sc[tt] = e;
                    esum += e;
                }
            }
            if (lane == 0) s_red[warp] = esum;
            __syncthreads();
            if (tid == 0) {
                float l = 0.f;
#pragma unroll
                for (int i = 0; i < 16; ++i) l += s_red[i];
                g_l[b * 2 + half] = l;
            }
            {
                int dp = tid & 127, tg = tid >> 7;   // 4 t-groups x 128 d-pairs
                const __half2* mb = reinterpret_cast<const __half2*>(
                    &g_memh[(size_t)(b * TENC + tbase + tg * 64) * DD]) + dp;
                const int sb = tg * 64;
                float ax = 0.f, ay = 0.f;
#pragma unroll 8
                for (int t = 0; t < 64; ++t) {
                    float2 mf = __half22float2(mb[t * 128]);
                    float sc = s_sc[sb + t];
                    ax = fmaf(sc, mf.x, ax);
                    ay = fmaf(sc, mf.y, ay);
                }
                s_cx[tg * 256 + dp * 2]     = ax;
                s_cx[tg * 256 + dp * 2 + 1] = ay;
            }
            __syncthreads();
            if (tid < 256)
                g_ctxpart[(b * 2 + half) * DD + tid] =
                    s_cx[tid] + s_cx[256 + tid] + s_cx[512 + tid] + s_cx[768 + tid];
        }
        grid_sync(++ep);

        // ============ P4: attention dense (normalizes ctx) ===================
        {
            const int ds = warp & 1, d = d0 + ds, bg = warp >> 1;
            float4 wa1[2], wa2[2];
#pragma unroll
            for (int c = 0; c < 2; ++c) {
                wa1[c] = *reinterpret_cast<const float4*>(&s_wa[ds * 2 * DD + c * 128 + lane * 4]);
                wa2[c] = *reinterpret_cast<const float4*>(&s_wa[ds * 2 * DD + DD + c * 128 + lane * 4]);
            }
#pragma unroll 2
            for (int bi = 0; bi < 8; ++bi) {
                int b = bg * 8 + bi;
                float inv_l = __fdividef(1.0f, g_l[b * 2] + g_l[b * 2 + 1]);
                const float4* hb = reinterpret_cast<const float4*>(&h1n[b * DD]);
                const float4* c0 = reinterpret_cast<const float4*>(&g_ctxpart[(b * 2 + 0) * DD]);
                const float4* c1 = reinterpret_cast<const float4*>(&g_ctxpart[(b * 2 + 1) * DD]);
                float a = 0;
#pragma unroll
                for (int c = 0; c < 2; ++c) {
                    float4 h4 = hb[c * 32 + lane];
                    a += dot4(h4, wa1[c]);
                    float4 a4 = c0[c * 32 + lane];
                    float4 b4 = c1[c * 32 + lane];
                    float4 x = make_float4((a4.x + b4.x) * inv_l, (a4.y + b4.y) * inv_l,
                                           (a4.z + b4.z) * inv_l, (a4.w + b4.w) * inv_l);
                    a += dot4(x, wa2[c]);
                }
                a = warp_sum_f(a);
                if (lane == 0) attn_[b * DD + d] = a;
            }
        }
        grid_sync(++ep);
    }

    // final y for step 399 (attn(399) lives in g_att[0])
    if (cta < 100) {
        const float* attc = g_att[0];
        const int jj = warp & 3, j = cta * 4 + jj, bg2 = warp >> 2;
        float4 wo0 = *reinterpret_cast<const float4*>(&s_wo[jj * DD + lane * 4]);
        float4 wo1 = *reinterpret_cast<const float4*>(&s_wo[jj * DD + 128 + lane * 4]);
        const float boj = bo[j];
        for (int bi = 0; bi < 16; ++bi) {
            int b = bg2 * 16 + bi;
            const float4* arow = reinterpret_cast<const float4*>(&attc[b * DD]);
            float a = dot4(arow[lane], wo0) + dot4(arow[32 + lane], wo1);
            a = warp_sum_f(a);
            if (lane == 0)
                out[(size_t)(b * TDEC + (TDEC - 1)) * ODIM + j] = a + boj;
        }
    }
}

// ---------------- launch ------------------------------------------------------
extern "C" void kernel_launch(void* const* d_in, const int* in_sizes, int n_in,
                              void* d_out, int out_size) {
    (void)in_sizes; (void)n_in; (void)out_size;
    const float* dec    = (const float*)d_in[0];
    const float* memory = (const float*)d_in[1];
    const float* W1  = (const float*)d_in[2];
    const float* b1  = (const float*)d_in[3];
    const float* W2  = (const float*)d_in[4];
    const float* b2  = (const float*)d_in[5];
    const float* k0  = (const float*)d_in[6];
    const float* r0  = (const float*)d_in[7];
    const float* bi0 = (const float*)d_in[8];
    const float* br0 = (const float*)d_in[9];
    const float* k1  = (const float*)d_in[10];
    const float* r1  = (const float*)d_in[11];
    const float* bi1 = (const float*)d_in[12];
    const float* br1 = (const float*)d_in[13];
    const float* Wq  = (const float*)d_in[14];
    const float* Wm  = (const float*)d_in[15];
    const float* v   = (const float*)d_in[16];
    const float* Wa  = (const float*)d_in[17];
    const float* Wo  = (const float*)d_in[18];
    const float* bo  = (const float*)d_in[19];
    float* out = (float*)d_out;

    static int s_attr_done = 0;
    if (!s_attr_done) {
        cudaFuncSetAttribute(dec_main_kernel,
                             cudaFuncAttributeMaxDynamicSharedMemorySize, 131072);
        s_attr_done = 1;
    }

    dec_setup_kernel<<<1024, 256>>>(k0, r0, k1, r1, Wq, Wa, Wo, memory);    // #1
    dec_gemm_kernel<<<912, 256>>>(dec, memory, W1, b1, Wm, W2, b2, 0);      // #2
    dec_gemm_kernel<<<200, 256>>>(dec, memory, W1, b1, Wm, W2, b2, 1);      // #3
    dec_main_kernel<<<GRID, NTH, 131072>>>(bi0, br0, bi1, br1, v, bo, out); // #4
}

// round 17
// speedup vs baseline: 1.0704x; 1.0234x over previous
#include <cuda_runtime.h>
#include <cuda_fp16.h>
#include <cstdint>
#include <cstddef>

#define BB   64
#define TDEC 400
#define TENC 512
#define DD   256
#define PRE  128
#define ODIM 400
#define CIN  (PRE + DD)   // 384
#define GRID 128
#define NTH  512

__device__ float  g_pre1[BB * TDEC * DD];
__device__ float  g_p[BB * TDEC * PRE];
__device__ float  g_keys[BB * TENC * DD];
__device__ __half g_memh[BB * TENC * DD];
__device__ float  g_k0T[3 * DD * CIN];
__device__ float  g_r0T[3 * DD * DD];
__device__ float  g_k1T[3 * DD * DD];
__device__ float  g_r1T[3 * DD * DD];
__device__ float  g_WqT[DD * DD];
__device__ float  g_WaT[DD * 2 * DD];     // [d][k], rows of 512
__device__ float  g_WoT[ODIM * DD];
__device__ float  g_h0[2][BB * DD];
__device__ float  g_h1[2][BB * DD];
__device__ float  g_att[2][BB * DD];
__device__ float  g_q[BB * DD];
__device__ float  g_ctxpart[BB * 2 * DD];   // unnormalized
__device__ float  g_l[BB * 2];              // partial softmax sums
__device__ unsigned g_barArrive;
__device__ unsigned g_pairCnt[BB];

__device__ __forceinline__ float warp_sum_f(float v) {
#pragma unroll
    for (int o = 16; o; o >>= 1) v += __shfl_xor_sync(0xffffffffu, v, o);
    return v;
}
__device__ __forceinline__ float sigm_f(float x) { return 1.0f / (1.0f + __expf(-x)); }
__device__ __forceinline__ float tanh_f(float x) {
    float e = __expf(2.0f * x);
    return 1.0f - __fdividef(2.0f, e + 1.0f);
}
__device__ __forceinline__ float tanha_f(float x) {
    float y;
    asm("tanh.approx.f32 %0, %1;" : "=f"(y) : "f"(x));
    return y;
}
__device__ __forceinline__ float dot4(float4 a, float4 b) {
    return fmaf(a.x, b.x, fmaf(a.y, b.y, fmaf(a.z, b.z, a.w * b.w)));
}
__device__ __forceinline__ void grid_sync(unsigned epoch) {
    __syncthreads();
    if (threadIdx.x == 0) {
        __threadfence();
        atomicAdd(&g_barArrive, 1u);
        unsigned tgt = epoch * (unsigned)GRID;
        while (*(volatile unsigned*)&g_barArrive < tgt) { __nanosleep(32); }
        __threadfence();
    }
    __syncthreads();
}

// -------- launch #1: init + all weight transposes + fp16 memory --------------
__global__ void dec_setup_kernel(const float* __restrict__ k0,
                                 const float* __restrict__ r0,
                                 const float* __restrict__ k1,
                                 const float* __restrict__ r1,
                                 const float* __restrict__ Wq,
                                 const float* __restrict__ Wa,
                                 const float* __restrict__ Wo,
                                 const float* __restrict__ memory) {
    int tid = blockIdx.x * blockDim.x + threadIdx.x;
    int nt = gridDim.x * blockDim.x;
    if (tid == 0) g_barArrive = 0;
    if (tid < BB) g_pairCnt[tid] = 0;
    for (int i = tid; i < BB * DD; i += nt) {
        g_h0[0][i] = 0.f; g_h1[0][i] = 0.f; g_att[0][i] = 0.f;
    }
    for (int i = tid; i < CIN * 768; i += nt) {
        int r = i / 768, c = i - r * 768;
        g_k0T[c * CIN + r] = k0[i];
    }
    for (int i = tid; i < DD * 768; i += nt) {
        int r = i / 768, c = i - r * 768;
        g_r0T[c * DD + r] = r0[i];
        g_k1T[c * DD + r] = k1[i];
        g_r1T[c * DD + r] = r1[i];
    }
    for (int i = tid; i < DD * DD; i += nt) {
        int r = i >> 8, c = i & 255;
        g_WqT[c * DD + r] = Wq[i];
    }
    for (int i = tid; i < 2 * DD * DD; i += nt) {
        int r = i >> 8, c = i & 255;
        g_WaT[c * 2 * DD + r] = Wa[i];
    }
    for (int i = tid; i < DD * ODIM; i += nt) {
        int r = i / ODIM, c = i - r * ODIM;
        g_WoT[c * DD + r] = Wo[i];
    }
    for (int i = tid; i < BB * TENC * DD; i += nt)
        g_memh[i] = __float2half(memory[i]);
}

// -------- launches #2/#3: SGEMM 128x128x8 (flat job decode) ------------------
__global__ __launch_bounds__(256) void dec_gemm_kernel(
    const float* __restrict__ dec, const float* __restrict__ memory,
    const float* __restrict__ W1, const float* __restrict__ b1,
    const float* __restrict__ Wm, const float* __restrict__ W2,
    const float* __restrict__ b2, int phase)
{
    const float *A, *Bm, *bias; float* C;
    int N, K, relu, t;
    if (phase == 0) {
        if (blockIdx.x < 400) {
            A = dec; Bm = W1; bias = b1; C = g_pre1;
            N = DD; K = ODIM; relu = 1; t = blockIdx.x;
        } else {
            A = memory; Bm = Wm; bias = 0; C = g_keys;
            N = DD; K = DD; relu = 0; t = blockIdx.x - 400;
        }
    } else {
        A = g_pre1; Bm = W2; bias = b2; C = g_p;
        N = PRE; K = DD; relu = 1; t = blockIdx.x;
    }
    int ntx = N >> 7;
    int n0 = (t % ntx) * 128, m0 = (t / ntx) * 128;

    __shared__ float As[8][128];
    __shared__ float Bs[8][128];
    const int tid = threadIdx.x;
    const int ty = tid / 16, txx = tid & 15;
    const int arow = tid >> 1, acol = (tid & 1) * 4;
    const int brow = tid >> 5, bcol = (tid & 31) * 4;
    float acc[8][8];
#pragma unroll
    for (int i = 0; i < 8; ++i)
#pragma unroll
        for (int j = 0; j < 8; ++j) acc[i][j] = 0.f;

    for (int k0i = 0; k0i < K; k0i += 8) {
        float4 a4 = *reinterpret_cast<const float4*>(&A[(size_t)(m0 + arow) * K + k0i + acol]);
        As[acol + 0][arow] = a4.x; As[acol + 1][arow] = a4.y;
        As[acol + 2][arow] = a4.z; As[acol + 3][arow] = a4.w;
        float4 b4 = *reinterpret_cast<const float4*>(&Bm[(size_t)(k0i + brow) * N + n0 + bcol]);
        *reinterpret_cast<float4*>(&Bs[brow][bcol]) = b4;
        __syncthreads();
#pragma unroll
        for (int k = 0; k < 8; ++k) {
            float af[8], bf[8];
#pragma unroll
            for (int i = 0; i < 8; ++i) af[i] = As[k][ty * 8 + i];
#pragma unroll
            for (int j = 0; j < 8; ++j) bf[j] = Bs[k][txx * 8 + j];
#pragma unroll
            for (int i = 0; i < 8; ++i)
#pragma unroll
                for (int j = 0; j < 8; ++j) acc[i][j] = fmaf(af[i], bf[j], acc[i][j]);
        }
        __syncthreads();
    }
#pragma unroll
    for (int i = 0; i < 8; ++i) {
        int m = m0 + ty * 8 + i;
#pragma unroll
        for (int j = 0; j < 8; ++j) {
            int n = n0 + txx * 8 + j;
            float c = acc[i][j] + (bias ? bias[n] : 0.f);
            if (relu) c = fmaxf(c, 0.f);
            C[(size_t)m * N + n] = c;
        }
    }
}

// -------- launch #4: persistent decoder (3 grid barriers/step) ----------------
__global__ __launch_bounds__(NTH) void dec_main_kernel(
    const float* __restrict__ bi0, const float* __restrict__ br0,
    const float* __restrict__ bi1, const float* __restrict__ br1,
    const float* __restrict__ v,   const float* __restrict__ bo,
    float* __restrict__ out)
{
    const int cta  = blockIdx.x;
    const int tid  = threadIdx.x;
    const int warp = tid >> 5, lane = tid & 31;
    const int d0   = cta * 2;
    unsigned ep = 0;

    __shared__ float s_k0[3 * 2 * CIN];
    __shared__ float s_r0[3 * 2 * DD];
    __shared__ float s_k1[3 * 2 * DD];
    __shared__ float s_r1[3 * 2 * DD];
    __shared__ float s_wo[4 * DD];
    __shared__ float s_q[DD];
    __shared__ float s_sc[DD];
    __shared__ float s_v[DD];
    __shared__ float s_cx[4 * DD];
    __shared__ float s_hc[2 * DD];          // staged [h1(b); ctx_norm(b)]
    __shared__ float s_red[16];

    for (int i = tid; i < 3 * 2 * CIN; i += NTH) {
        int g = i / (2 * CIN); int rem = i - g * 2 * CIN;
        int ds = rem / CIN;    int k = rem - ds * CIN;
        s_k0[i] = g_k0T[(g * DD + d0 + ds) * CIN + k];
    }
    for (int i = tid; i < 3 * 2 * DD; i += NTH) {
        int g = i / (2 * DD); int rem = i - g * 2 * DD;
        int ds = rem / DD;    int k = rem - ds * DD;
        s_r0[i] = g_r0T[(g * DD + d0 + ds) * DD + k];
        s_k1[i] = g_k1T[(g * DD + d0 + ds) * DD + k];
        s_r1[i] = g_r1T[(g * DD + d0 + ds) * DD + k];
    }
    if (cta < 100) {
        for (int i = tid; i < 4 * DD; i += NTH) {
            int jj = i / DD; int k = i - jj * DD;
            s_wo[i] = g_WoT[(cta * 4 + jj) * DD + k];
        }
    }
    for (int i = tid; i < DD; i += NTH) s_v[i] = v[i];
    __syncthreads();

    float S = 0.f;
    for (int i = 0; i < DD; ++i) S += fabsf(s_v[i]);
    float4 v4[2];
#pragma unroll
    for (int c = 0; c < 2; ++c)
        v4[c] = *reinterpret_cast<const float4*>(&s_v[c * 128 + lane * 4]);

    for (int step = 0; step < TDEC; ++step) {
        const int par = step & 1;
        const float* h0c  = g_h0[par];    float* h0n  = g_h0[par ^ 1];
        const float* h1c  = g_h1[par];    float* h1n  = g_h1[par ^ 1];
        const float* attc = g_att[par];   float* attn_ = g_att[par ^ 1];

        // ============ P1: GRU0 (+ output dense for step-1) ==================
        {
            const int ds = warp & 1, d = d0 + ds, bg = warp >> 1;
            float4 wz[3], wr_[3], wh[3], uz[2], ur_[2], uh[2];
#pragma unroll
            for (int c = 0; c < 3; ++c) {
                wz[c]  = *reinterpret_cast<const float4*>(&s_k0[(0 * 2 + ds) * CIN + c * 128 + lane * 4]);
                wr_[c] = *reinterpret_cast<const float4*>(&s_k0[(1 * 2 + ds) * CIN + c * 128 + lane * 4]);
                wh[c]  = *reinterpret_cast<const float4*>(&s_k0[(2 * 2 + ds) * CIN + c * 128 + lane * 4]);
            }
#pragma unroll
            for (int c = 0; c < 2; ++c) {
                uz[c]  = *reinterpret_cast<const float4*>(&s_r0[(0 * 2 + ds) * DD + c * 128 + lane * 4]);
                ur_[c] = *reinterpret_cast<const float4*>(&s_r0[(1 * 2 + ds) * DD + c * 128 + lane * 4]);
                uh[c]  = *reinterpret_cast<const float4*>(&s_r0[(2 * 2 + ds) * DD + c * 128 + lane * 4]);
            }
            const float bz  = bi0[d] + br0[d];
            const float brg = bi0[DD + d] + br0[DD + d];
            const float bih = bi0[2 * DD + d], brh = br0[2 * DD + d];
#pragma unroll 2
            for (int bi = 0; bi < 8; ++bi) {
                int b = bg * 8 + bi;
                const float4* pb = reinterpret_cast<const float4*>(&g_p[(b * TDEC + step) * PRE]);
                const float4* ab = reinterpret_cast<const float4*>(&attc[b * DD]);
                const float4* hb = reinterpret_cast<const float4*>(&h0c[b * DD]);
                float4 x0 = pb[lane];
                float4 x1 = ab[lane], x2 = ab[32 + lane];
                float4 h1v = hb[lane], h2v = hb[32 + lane];
                float az = dot4(x0, wz[0])  + dot4(x1, wz[1])  + dot4(x2, wz[2]);
                float ar = dot4(x0, wr_[0]) + dot4(x1, wr_[1]) + dot4(x2, wr_[2]);
                float ah = dot4(x0, wh[0])  + dot4(x1, wh[1])  + dot4(x2, wh[2]);
                float gz = dot4(h1v, uz[0])  + dot4(h2v, uz[1]);
                float gr = dot4(h1v, ur_[0]) + dot4(h2v, ur_[1]);
                float gh = dot4(h1v, uh[0])  + dot4(h2v, uh[1]);
                float sz = az + gz, sr = ar + gr;
#pragma unroll
                for (int off = 16; off; off >>= 1) {
                    sz += __shfl_xor_sync(0xffffffffu, sz, off);
                    sr += __shfl_xor_sync(0xffffffffu, sr, off);
                    ah += __shfl_xor_sync(0xffffffffu, ah, off);
                    gh += __shfl_xor_sync(0xffffffffu, gh, off);
                }
                if (lane == 0) {
                    float z = sigm_f(sz + bz);
                    float r = sigm_f(sr + brg);
                    float hc = tanh_f(ah + bih + r * (gh + brh));
                    h0n[b * DD + d] = z * h0c[b * DD + d] + (1.0f - z) * hc;
                }
            }
            if (cta < 100 && step > 0) {
                const int jj = warp & 3, j = cta * 4 + jj, bg2 = warp >> 2;
                float4 wo0 = *reinterpret_cast<const float4*>(&s_wo[jj * DD + lane * 4]);
                float4 wo1 = *reinterpret_cast<const float4*>(&s_wo[jj * DD + 128 + lane * 4]);
                const float boj = bo[j];
#pragma unroll 2
                for (int bi = 0; bi < 16; ++bi) {
                    int b = bg2 * 16 + bi;
                    const float4* arow = reinterpret_cast<const float4*>(&attc[b * DD]);
                    float a = dot4(arow[lane], wo0) + dot4(arow[32 + lane], wo1);
                    a = warp_sum_f(a);
                    if (lane == 0)
                        out[(size_t)(b * TDEC + (step - 1)) * ODIM + j] = a + boj;
                }
            }
        }
        grid_sync(++ep);

        // ============ P2: GRU1 ===============================================
        {
            const int ds = warp & 1, d = d0 + ds, bg = warp >> 1;
            float4 wk[3][2], ur[3][2];
#pragma unroll
            for (int g = 0; g < 3; ++g)
#pragma unroll
                for (int c = 0; c < 2; ++c) {
                    wk[g][c] = *reinterpret_cast<const float4*>(&s_k1[(g * 2 + ds) * DD + c * 128 + lane * 4]);
                    ur[g][c] = *reinterpret_cast<const float4*>(&s_r1[(g * 2 + ds) * DD + c * 128 + lane * 4]);
                }
            const float bz  = bi1[d] + br1[d];
            const float brg = bi1[DD + d] + br1[DD + d];
            const float bih = bi1[2 * DD + d], brh = br1[2 * DD + d];
#pragma unroll 2
            for (int bi = 0; bi < 8; ++bi) {
                int b = bg * 8 + bi;
                const float4* xb = reinterpret_cast<const float4*>(&h0n[b * DD]);
                const float4* hb = reinterpret_cast<const float4*>(&h1c[b * DD]);
                float4 x0 = xb[lane], x1 = xb[32 + lane];
                float4 h0v = hb[lane], h1v = hb[32 + lane];
                float az = dot4(x0, wk[0][0]) + dot4(x1, wk[0][1]);
                float ar = dot4(x0, wk[1][0]) + dot4(x1, wk[1][1]);
                float ah = dot4(x0, wk[2][0]) + dot4(x1, wk[2][1]);
                float gz = dot4(h0v, ur[0][0]) + dot4(h1v, ur[0][1]);
                float gr = dot4(h0v, ur[1][0]) + dot4(h1v, ur[1][1]);
                float gh = dot4(h0v, ur[2][0]) + dot4(h1v, ur[2][1]);
                float sz = az + gz, sr = ar + gr;
#pragma unroll
                for (int off = 16; off; off >>= 1) {
                    sz += __shfl_xor_sync(0xffffffffu, sz, off);
                    sr += __shfl_xor_sync(0xffffffffu, sr, off);
                    ah += __shfl_xor_sync(0xffffffffu, ah, off);
                    gh += __shfl_xor_sync(0xffffffffu, gh, off);
                }
                if (lane == 0) {
                    float z = sigm_f(sz + bz);
                    float r = sigm_f(sr + brg);
                    float hc = tanh_f(ah + bih + r * (gh + brh));
                    h1n[b * DD + d] = z * h1c[b * DD + d] + (1.0f - z) * hc;
                }
            }
        }
        grid_sync(++ep);

        // ====== P3: q-half + scores + ctx + (fused) attention dense =========
        {
            const int b = cta >> 1, half = cta & 1;
            const int tbase = half * 256;
            {
                const float4* hb = reinterpret_cast<const float4*>(&h1n[b * DD]);
                float4 h0v = hb[lane], h1v = hb[32 + lane];
#pragma unroll 2
                for (int qi = 0; qi < 8; ++qi) {
                    int dq = half * 128 + warp * 8 + qi;
                    const float4* wr = reinterpret_cast<const float4*>(&g_WqT[dq * DD]);
                    float a = dot4(h0v, wr[lane]) + dot4(h1v, wr[32 + lane]);
                    a = warp_sum_f(a);
                    if (lane == 0) { g_q[b * DD + dq] = a; s_q[dq] = a; }
                }
            }
            __syncthreads();
            // pair sync #1: q halves exchanged (4 arrivals/b/step total)
            if (tid == 0) {
                __threadfence();
                atomicAdd(&g_pairCnt[b], 1u);
                unsigned tgt = 4u * (unsigned)step + 2u;
                while (*(volatile unsigned*)&g_pairCnt[b] < tgt) { __nanosleep(32); }
                __threadfence();
            }
            __syncthreads();
            if (tid < 128) {
                int oh = half ^ 1;
                s_q[oh * 128 + tid] = g_q[b * DD + oh * 128 + tid];
            }
            __syncthreads();
            float4 q4[2];
#pragma unroll
            for (int c = 0; c < 2; ++c)
                q4[c] = *reinterpret_cast<const float4*>(&s_q[c * 128 + lane * 4]);
            float esum = 0.f;
#pragma unroll 2
            for (int ti = 0; ti < 16; ++ti) {
                int tt = warp * 16 + ti;
                const float* krow = &g_keys[(size_t)(b * TENC + tbase + tt) * DD];
                float a = 0;
#pragma unroll
                for (int c = 0; c < 2; ++c) {
                    float4 kk = *reinterpret_cast<const float4*>(&krow[c * 128 + lane * 4]);
                    a += tanha_f(kk.x + q4[c].x) * v4[c].x;
                    a += tanha_f(kk.y + q4[c].y) * v4[c].y;
                    a += tanha_f(kk.z + q4[c].z) * v4[c].z;
                    a += tanha_f(kk.w + q4[c].w) * v4[c].w;
                }
                a = warp_sum_f(a);
                if (lane == 0) {
                    float e = __expf(a - S);
                    s_sc[tt] = e;
                    esum += e;
                }
            }
            if (lane == 0) s_red[warp] = esum;
            __syncthreads();
            if (tid == 0) {
                float l = 0.f;
#pragma unroll
                for (int i = 0; i < 16; ++i) l += s_red[i];
                g_l[b * 2 + half] = l;
            }
            {
                int dp = tid & 127, tg = tid >> 7;   // 4 t-groups x 128 d-pairs
                const __half2* mb = reinterpret_cast<const __half2*>(
                    &g_memh[(size_t)(b * TENC + tbase + tg * 64) * DD]) + dp;
                const int sb = tg * 64;
                float ax = 0.f, ay = 0.f;
#pragma unroll 8
                for (int t = 0; t < 64; ++t) {
                    float2 mf = __half22float2(mb[t * 128]);
                    float sc = s_sc[sb + t];
                    ax = fmaf(sc, mf.x, ax);
                    ay = fmaf(sc, mf.y, ay);
                }
                s_cx[tg * 256 + dp * 2]     = ax;
                s_cx[tg * 256 + dp * 2 + 1] = ay;
            }
            __syncthreads();
            if (tid < 256)
                g_ctxpart[(b * 2 + half) * DD + tid] =
                    s_cx[tid] + s_cx[256 + tid] + s_cx[512 + tid] + s_cx[768 + tid];
            __syncthreads();
            // pair sync #2: ctx halves + l exchanged
            if (tid == 0) {
                __threadfence();
                atomicAdd(&g_pairCnt[b], 1u);
                unsigned tgt = 4u * (unsigned)step + 4u;
                while (*(volatile unsigned*)&g_pairCnt[b] < tgt) { __nanosleep(32); }
                __threadfence();
            }
            __syncthreads();
            // stage [h1(b); (c0+c1)*inv_l] into s_hc (512 floats)
            {
                float inv_l = __fdividef(1.0f, g_l[b * 2] + g_l[b * 2 + 1]);
                if (tid < 128) {
                    float4* dst = reinterpret_cast<float4*>(s_hc);
                    if (tid < 64) {
                        dst[tid] = reinterpret_cast<const float4*>(&h1n[b * DD])[tid];
                    } else {
                        int i = tid - 64;
                        float4 a4 = reinterpret_cast<const float4*>(&g_ctxpart[(b * 2 + 0) * DD])[i];
                        float4 b4 = reinterpret_cast<const float4*>(&g_ctxpart[(b * 2 + 1) * DD])[i];
                        dst[64 + i] = make_float4((a4.x + b4.x) * inv_l, (a4.y + b4.y) * inv_l,
                                                  (a4.z + b4.z) * inv_l, (a4.w + b4.w) * inv_l);
                    }
                }
            }
            __syncthreads();
            // attn[b, half*128 .. +128): 16 warps x 8 outputs, WaT rows from L2
            {
                const float4* hc4 = reinterpret_cast<const float4*>(s_hc);
                float4 in0 = hc4[lane],      in1 = hc4[32 + lane];
                float4 in2 = hc4[64 + lane], in3 = hc4[96 + lane];
#pragma unroll 2
                for (int qi = 0; qi < 8; ++qi) {
                    int dq = half * 128 + warp * 8 + qi;
                    const float4* wr = reinterpret_cast<const float4*>(&g_WaT[dq * 2 * DD]);
                    float a = dot4(in0, wr[lane])      + dot4(in1, wr[32 + lane])
                            + dot4(in2, wr[64 + lane]) + dot4(in3, wr[96 + lane]);
                    a = warp_sum_f(a);
                    if (lane == 0) attn_[b * DD + dq] = a;
                }
            }
        }
        grid_sync(++ep);
    }

    // final y for step 399 (attn(399) lives in g_att[0])
    if (cta < 100) {
        const float* attc = g_att[0];
        const int jj = warp & 3, j = cta * 4 + jj, bg2 = warp >> 2;
        float4 wo0 = *reinterpret_cast<const float4*>(&s_wo[jj * DD + lane * 4]);
        float4 wo1 = *reinterpret_cast<const float4*>(&s_wo[jj * DD + 128 + lane * 4]);
        const float boj = bo[j];
        for (int bi = 0; bi < 16; ++bi) {
            int b = bg2 * 16 + bi;
            const float4* arow = reinterpret_cast<const float4*>(&attc[b * DD]);
            float a = dot4(arow[lane], wo0) + dot4(arow[32 + lane], wo1);
            a = warp_sum_f(a);
            if (lane == 0)
                out[(size_t)(b * TDEC + (TDEC - 1)) * ODIM + j] = a + boj;
        }
    }
}

// ---------------- launch ------------------------------------------------------
extern "C" void kernel_launch(void* const* d_in, const int* in_sizes, int n_in,
                              void* d_out, int out_size) {
    (void)in_sizes; (void)n_in; (void)out_size;
    const float* dec    = (const float*)d_in[0];
    const float* memory = (const float*)d_in[1];
    const float* W1  = (const float*)d_in[2];
    const float* b1  = (const float*)d_in[3];
    const float* W2  = (const float*)d_in[4];
    const float* b2  = (const float*)d_in[5];
    const float* k0  = (const float*)d_in[6];
    const float* r0  = (const float*)d_in[7];
    const float* bi0 = (const float*)d_in[8];
    const float* br0 = (const float*)d_in[9];
    const float* k1  = (const float*)d_in[10];
    const float* r1  = (const float*)d_in[11];
    const float* bi1 = (const float*)d_in[12];
    const float* br1 = (const float*)d_in[13];
    const float* Wq  = (const float*)d_in[14];
    const float* Wm  = (const float*)d_in[15];
    const float* v   = (const float*)d_in[16];
    const float* Wa  = (const float*)d_in[17];
    const float* Wo  = (const float*)d_in[18];
    const float* bo  = (const float*)d_in[19];
    float* out = (float*)d_out;

    dec_setup_kernel<<<1024, 256>>>(k0, r0, k1, r1, Wq, Wa, Wo, memory);    // #1
    dec_gemm_kernel<<<912, 256>>>(dec, memory, W1, b1, Wm, W2, b2, 0);      // #2
    dec_gemm_kernel<<<200, 256>>>(dec, memory, W1, b1, Wm, W2, b2, 1);      // #3
    dec_main_kernel<<<GRID, NTH>>>(bi0, br0, bi1, br1, v, bo, out);         // #4
}